// round 1
// baseline (speedup 1.0000x reference)
#include <cuda_runtime.h>
#include <cuda_bf16.h>
#include <math_constants.h>

#define Bc 2
#define Cc 256
#define Hc 256
#define Wc 256
#define MIDc 16
#define HWc 65536

typedef unsigned long long u64;

__device__ float g_base[4 * 49];
__device__ float g_xlow[(size_t)Bc * HWc * MIDc];    // [b][p][m] interleaved
__device__ float g_outlow[(size_t)Bc * HWc * MIDc];  // [b][p][m] interleaved

__device__ __forceinline__ u64 pack2(float lo, float hi) {
    u64 r; asm("mov.b64 %0, {%1,%2};" : "=l"(r) : "f"(lo), "f"(hi)); return r;
}
__device__ __forceinline__ void unpack2(u64 v, float& lo, float& hi) {
    asm("mov.b64 {%0,%1}, %2;" : "=f"(lo), "=f"(hi) : "l"(v));
}
__device__ __forceinline__ void fma2(u64& d, u64 a, u64 b) {
    asm("fma.rn.f32x2 %0, %1, %2, %0;" : "+l"(d) : "l"(a), "l"(b));
}
__device__ __forceinline__ u64 add2(u64 a, u64 b) {
    u64 r; asm("add.rn.f32x2 %0, %1, %2;" : "=l"(r) : "l"(a), "l"(b)); return r;
}

// ---------------------------------------------------------------------------
// Kernel 0: build the 4 oriented anisotropic Gaussian base kernels.
// ---------------------------------------------------------------------------
__global__ void k_base() {
    int k = threadIdx.x;
    if (k >= 4) return;
    float theta = (float)k * (float)(CUDART_PI / 4.0);
    float c = cosf(theta), s = sinf(theta);
    float v[49];
    float sum = 0.f;
    for (int i = 0; i < 7; i++) {
        for (int j = 0; j < 7; j++) {
            float xx = (float)(i - 3), yy = (float)(j - 3);
            float xr = xx * c + yy * s;
            float yr = -xx * s + yy * c;
            float e = expf(-(xr * xr * (1.f / 12.5f) + yr * yr * 0.5f));
            v[i * 7 + j] = e;
            sum += e;
        }
    }
    float inv = 1.f / sum;
    for (int t = 0; t < 49; t++) g_base[k * 49 + t] = v[t] * inv;
}

// ---------------------------------------------------------------------------
// Kernel 1: 1x1 reduce conv  x[b,c,h,w] * rw[m,c] -> xlow[b,p,m] (interleaved)
// 128 threads, 4 pixels/thread, f32x2 packed accumulation.
// ---------------------------------------------------------------------------
__global__ __launch_bounds__(128) void k_reduce(const float* __restrict__ x,
                                                const float* __restrict__ rw) {
    __shared__ __align__(16) float2 s_rw[4096];  // [c][m] dup-packed, 32 KB
    int tid = threadIdx.x;
    for (int i = tid; i < 4096; i += 128) {
        int c = i >> 4, m = i & 15;
        float v = rw[m * 256 + c];
        s_rw[i] = make_float2(v, v);
    }
    __syncthreads();

    size_t p4 = ((size_t)blockIdx.x * 128 + tid) * 4;  // global pixel (over B*HW)
    int b = (int)(p4 >> 16);
    int p = (int)(p4 & 65535);
    const char* xb = (const char*)(x + (size_t)b * Cc * HWc + p);
    const ulonglong2* srw = (const ulonglong2*)s_rw;

    u64 a0[16], a1[16];
#pragma unroll
    for (int m = 0; m < 16; m++) { a0[m] = 0ull; a1[m] = 0ull; }

#pragma unroll 4
    for (int c = 0; c < 256; c++) {
        ulonglong2 xv = *(const ulonglong2*)(xb + (size_t)c * (HWc * 4));  // px0..3
#pragma unroll
        for (int mm = 0; mm < 8; mm++) {
            ulonglong2 w = srw[c * 8 + mm];
            fma2(a0[2 * mm],     xv.x, w.x);
            fma2(a1[2 * mm],     xv.y, w.x);
            fma2(a0[2 * mm + 1], xv.x, w.y);
            fma2(a1[2 * mm + 1], xv.y, w.y);
        }
    }

    float f0[16], f1[16], f2[16], f3[16];
#pragma unroll
    for (int m = 0; m < 16; m++) {
        unpack2(a0[m], f0[m], f1[m]);
        unpack2(a1[m], f2[m], f3[m]);
    }
    float4* dst = (float4*)(g_xlow + p4 * 16);
#pragma unroll
    for (int q = 0; q < 4; q++) {
        dst[0 * 4 + q] = make_float4(f0[4 * q], f0[4 * q + 1], f0[4 * q + 2], f0[4 * q + 3]);
        dst[1 * 4 + q] = make_float4(f1[4 * q], f1[4 * q + 1], f1[4 * q + 2], f1[4 * q + 3]);
        dst[2 * 4 + q] = make_float4(f2[4 * q], f2[4 * q + 1], f2[4 * q + 2], f2[4 * q + 3]);
        dst[3 * 4 + q] = make_float4(f3[4 * q], f3[4 * q + 1], f3[4 * q + 2], f3[4 * q + 3]);
    }
}

// ---------------------------------------------------------------------------
// Kernel 2: fused angle-MLP + softmax + kernel-combine + 7x7 directional conv.
// Tile 32x8 pixels, halo 3 (reflect), all 16 channels in smem with a rotation
// swizzle so lane-consecutive LDS.128 reads are bank-conflict-free.
// ---------------------------------------------------------------------------
__global__ __launch_bounds__(256) void k_conv(const float* __restrict__ angle,
                                              const float* __restrict__ w1,
                                              const float* __restrict__ b1,
                                              const float* __restrict__ w2,
                                              const float* __restrict__ b2) {
    __shared__ __align__(16) float s_x[14 * 38 * 16];  // 34 KB, swizzled
    __shared__ float s_base[196];
    __shared__ float s_w1[16], s_b1[8], s_w2[32], s_b2[4];

    int tx = threadIdx.x, ty = threadIdx.y;
    int tid = ty * 32 + tx;
    int x0 = blockIdx.x * 32, y0 = blockIdx.y * 8, b = blockIdx.z;

    if (tid < 196) s_base[tid] = g_base[tid];
    if (tid < 16) s_w1[tid] = w1[tid];
    if (tid < 8)  s_b1[tid] = b1[tid];
    if (tid < 32) s_w2[tid] = w2[tid];
    if (tid < 4)  s_b2[tid] = b2[tid];

    // Load halo tile with reflect padding, swizzled store.
    for (int i = tid; i < 14 * 38 * 4; i += 256) {
        int pl = i >> 2, g = i & 3;
        int ry = pl / 38, rx = pl - ry * 38;
        int gy = y0 + ry - 3; gy = gy < 0 ? -gy : (gy > 255 ? 510 - gy : gy);
        int gx = x0 + rx - 3; gx = gx < 0 ? -gx : (gx > 255 ? 510 - gx : gx);
        const float4* src = (const float4*)(g_xlow + ((size_t)((b << 16) + (gy << 8) + gx)) * 16);
        int slot = (g + (pl >> 1)) & 3;
        *(float4*)(s_x + pl * 16 + slot * 4) = src[g];
    }
    __syncthreads();

    int px = x0 + tx, py = y0 + ty;

    // Per-pixel mixing weights: MLP(2->8->4) + softmax.
    float a = angle[(size_t)((b << 16) + (py << 8) + px)];
    float sn, cs;
    sincosf(2.f * a, &sn, &cs);
    float hb[8];
#pragma unroll
    for (int j = 0; j < 8; j++)
        hb[j] = fmaxf(0.f, fmaf(sn, s_w1[2 * j], fmaf(cs, s_w1[2 * j + 1], s_b1[j])));
    float lg[4];
#pragma unroll
    for (int o = 0; o < 4; o++) {
        float t = s_b2[o];
#pragma unroll
        for (int j = 0; j < 8; j++) t = fmaf(hb[j], s_w2[o * 8 + j], t);
        lg[o] = t;
    }
    float mx = fmaxf(fmaxf(lg[0], lg[1]), fmaxf(lg[2], lg[3]));
    float wk[4];
    float sum = 0.f;
#pragma unroll
    for (int o = 0; o < 4; o++) { wk[o] = expf(lg[o] - mx); sum += wk[o]; }
    float inv = 1.f / sum;
#pragma unroll
    for (int o = 0; o < 4; o++) wk[o] *= inv;

    // Combined per-pixel 7x7 kernel.
    float ck[49];
#pragma unroll
    for (int t = 0; t < 49; t++)
        ck[t] = fmaf(wk[3], s_base[147 + t],
                fmaf(wk[2], s_base[98 + t],
                fmaf(wk[1], s_base[49 + t], wk[0] * s_base[t])));

    u64 acc[8];
#pragma unroll
    for (int q = 0; q < 8; q++) acc[q] = 0ull;
    const ulonglong2* sx2 = (const ulonglong2*)s_x;

#pragma unroll
    for (int i = 0; i < 7; i++) {
#pragma unroll
        for (int j = 0; j < 7; j++) {
            int pl = (ty + i) * 38 + tx + j;
            int base4 = pl * 4;
            int r = (pl >> 1) & 3;
            u64 ckd = pack2(ck[i * 7 + j], ck[i * 7 + j]);
            ulonglong2 v0 = sx2[base4 + ((0 + r) & 3)];
            ulonglong2 v1 = sx2[base4 + ((1 + r) & 3)];
            ulonglong2 v2 = sx2[base4 + ((2 + r) & 3)];
            ulonglong2 v3 = sx2[base4 + ((3 + r) & 3)];
            fma2(acc[0], v0.x, ckd); fma2(acc[1], v0.y, ckd);
            fma2(acc[2], v1.x, ckd); fma2(acc[3], v1.y, ckd);
            fma2(acc[4], v2.x, ckd); fma2(acc[5], v2.y, ckd);
            fma2(acc[6], v3.x, ckd); fma2(acc[7], v3.y, ckd);
        }
    }

    float f[16];
#pragma unroll
    for (int q = 0; q < 8; q++) unpack2(acc[q], f[2 * q], f[2 * q + 1]);
    float4* dst = (float4*)(g_outlow + (size_t)((b << 16) + (py << 8) + px) * 16);
#pragma unroll
    for (int q = 0; q < 4; q++)
        dst[q] = make_float4(f[4 * q], f[4 * q + 1], f[4 * q + 2], f[4 * q + 3]);
}

// ---------------------------------------------------------------------------
// Kernel 3: 1x1 expand conv  outlow[b,p,m] * ew[c,m] -> out[b,c,h,w]
// 128 threads, 4 pixels/thread, f32x2 packed, STG.128 per c.
// ---------------------------------------------------------------------------
__global__ __launch_bounds__(128) void k_expand(const float* __restrict__ ew,
                                                float* __restrict__ out) {
    __shared__ __align__(16) float2 s_ew[4096];  // [c][m] dup-packed, 32 KB
    int tid = threadIdx.x;
    for (int i = tid; i < 4096; i += 128) {
        float v = ew[i];
        s_ew[i] = make_float2(v, v);
    }
    __syncthreads();

    size_t p4 = ((size_t)blockIdx.x * 128 + tid) * 4;
    int b = (int)(p4 >> 16);
    int p = (int)(p4 & 65535);

    const float4* ol = (const float4*)(g_outlow + p4 * 16);
    float fv[4][16];
#pragma unroll
    for (int pxi = 0; pxi < 4; pxi++) {
#pragma unroll
        for (int k = 0; k < 4; k++) {
            float4 t = ol[pxi * 4 + k];
            fv[pxi][4 * k] = t.x; fv[pxi][4 * k + 1] = t.y;
            fv[pxi][4 * k + 2] = t.z; fv[pxi][4 * k + 3] = t.w;
        }
    }
    u64 x01[16], x23[16];
#pragma unroll
    for (int m = 0; m < 16; m++) {
        x01[m] = pack2(fv[0][m], fv[1][m]);
        x23[m] = pack2(fv[2][m], fv[3][m]);
    }

    const ulonglong2* sew = (const ulonglong2*)s_ew;
    float* ob = out + (size_t)b * Cc * HWc + p;

#pragma unroll 2
    for (int c = 0; c < 256; c++) {
        u64 aA = 0ull, aB = 0ull, aC = 0ull, aD = 0ull;
#pragma unroll
        for (int mm = 0; mm < 8; mm++) {
            ulonglong2 w = sew[c * 8 + mm];
            fma2(aA, x01[2 * mm],     w.x);
            fma2(aC, x23[2 * mm],     w.x);
            fma2(aB, x01[2 * mm + 1], w.y);
            fma2(aD, x23[2 * mm + 1], w.y);
        }
        ulonglong2 r;
        r.x = add2(aA, aB);
        r.y = add2(aC, aD);
        *(ulonglong2*)(ob + (size_t)c * HWc) = r;
    }
}

// ---------------------------------------------------------------------------
extern "C" void kernel_launch(void* const* d_in, const int* in_sizes, int n_in,
                              void* d_out, int out_size) {
    const float* x     = (const float*)d_in[0];
    const float* angle = (const float*)d_in[1];
    const float* rw    = (const float*)d_in[2];
    const float* ew    = (const float*)d_in[3];
    const float* w1    = (const float*)d_in[4];
    const float* b1    = (const float*)d_in[5];
    const float* w2    = (const float*)d_in[6];
    const float* b2    = (const float*)d_in[7];
    float* out = (float*)d_out;

    k_base<<<1, 32>>>();
    k_reduce<<<256, 128>>>(x, rw);
    k_conv<<<dim3(8, 32, 2), dim3(32, 8)>>>(angle, w1, b1, w2, b2);
    k_expand<<<256, 128>>>(ew, out);
}

// round 4
// speedup vs baseline: 1.1823x; 1.1823x over previous
#include <cuda_runtime.h>
#include <cuda_bf16.h>
#include <math_constants.h>

#define Bc 2
#define Cc 256
#define Hc 256
#define Wc 256
#define MIDc 16
#define HWc 65536

typedef unsigned long long u64;

__device__ float g_xlow[(size_t)Bc * HWc * MIDc];    // [b][p][m] interleaved
__device__ float g_outlow[(size_t)Bc * HWc * MIDc];  // [b][p][m] interleaved

__device__ __forceinline__ u64 pack2(float lo, float hi) {
    u64 r; asm("mov.b64 %0, {%1,%2};" : "=l"(r) : "f"(lo), "f"(hi)); return r;
}
__device__ __forceinline__ void unpack2(u64 v, float& lo, float& hi) {
    asm("mov.b64 {%0,%1}, %2;" : "=f"(lo), "=f"(hi) : "l"(v));
}
__device__ __forceinline__ void fma2(u64& d, u64 a, u64 b) {
    asm("fma.rn.f32x2 %0, %1, %2, %0;" : "+l"(d) : "l"(a), "l"(b));
}
__device__ __forceinline__ u64 add2(u64 a, u64 b) {
    u64 r; asm("add.rn.f32x2 %0, %1, %2;" : "=l"(r) : "l"(a), "l"(b)); return r;
}

// ---------------------------------------------------------------------------
// Kernel 1: 1x1 reduce conv  x[b,c,h,w] * rw[m,c] -> xlow[b,p,m] (interleaved)
// 1 pixel/thread, m-pair f32x2 packing. 512 blocks x 256 threads.
// ---------------------------------------------------------------------------
__global__ __launch_bounds__(256) void k_reduce(const float* __restrict__ x,
                                                const float* __restrict__ rw) {
    __shared__ __align__(16) float s_rw[4096];  // [c][m], 16 KB
    int tid = threadIdx.x;
    for (int i = tid; i < 4096; i += 256) {
        int c = i >> 4, m = i & 15;
        s_rw[i] = rw[m * 256 + c];
    }
    __syncthreads();

    int gp = blockIdx.x * 256 + tid;            // global pixel over B*HW
    int b = gp >> 16, p = gp & 65535;
    const float* xb = x + (size_t)b * Cc * HWc + p;
    const ulonglong2* srw = (const ulonglong2*)s_rw;

    u64 acc[8];
#pragma unroll
    for (int m = 0; m < 8; m++) acc[m] = 0ull;

#pragma unroll 4
    for (int c = 0; c < 256; c++) {
        float xv = __ldg(xb + (size_t)c * HWc);
        u64 xd = pack2(xv, xv);
        ulonglong2 w0 = srw[c * 4 + 0];
        ulonglong2 w1 = srw[c * 4 + 1];
        ulonglong2 w2 = srw[c * 4 + 2];
        ulonglong2 w3 = srw[c * 4 + 3];
        fma2(acc[0], xd, w0.x); fma2(acc[1], xd, w0.y);
        fma2(acc[2], xd, w1.x); fma2(acc[3], xd, w1.y);
        fma2(acc[4], xd, w2.x); fma2(acc[5], xd, w2.y);
        fma2(acc[6], xd, w3.x); fma2(acc[7], xd, w3.y);
    }

    ulonglong2* dst = (ulonglong2*)(g_xlow + (size_t)gp * 16);
    ulonglong2 r0; r0.x = acc[0]; r0.y = acc[1]; dst[0] = r0;
    ulonglong2 r1; r1.x = acc[2]; r1.y = acc[3]; dst[1] = r1;
    ulonglong2 r2; r2.x = acc[4]; r2.y = acc[5]; dst[2] = r2;
    ulonglong2 r3; r3.x = acc[6]; r3.y = acc[7]; dst[3] = r3;
}

// ---------------------------------------------------------------------------
// Kernel 2: fused base-kernel build + angle-MLP + softmax + 7x7 directional
// conv. Tile 32x8 pixels, halo 3 (reflect), 16 channels in smem with rotation
// swizzle for conflict-free LDS.128.
// ---------------------------------------------------------------------------
__global__ __launch_bounds__(256) void k_conv(const float* __restrict__ angle,
                                              const float* __restrict__ w1,
                                              const float* __restrict__ b1,
                                              const float* __restrict__ w2,
                                              const float* __restrict__ b2) {
    __shared__ __align__(16) float s_x[14 * 38 * 16];  // 34 KB, swizzled
    __shared__ float s_base[196];
    __shared__ float s_sinv[4];
    __shared__ float s_w1[16], s_b1[8], s_w2[32], s_b2[4];

    int tx = threadIdx.x, ty = threadIdx.y;
    int tid = ty * 32 + tx;
    int x0 = blockIdx.x * 32, y0 = blockIdx.y * 8, b = blockIdx.z;

    // Build the 4 oriented anisotropic Gaussian kernels (unnormalized).
    if (tid < 196) {
        int k = tid / 49, r = tid - k * 49;
        int ii = r / 7 - 3, jj = r % 7 - 3;
        float theta = (float)k * (float)(CUDART_PI / 4.0);
        float cth, sth;
        sincosf(theta, &sth, &cth);
        float xr = (float)ii * cth + (float)jj * sth;
        float yr = -(float)ii * sth + (float)jj * cth;
        s_base[tid] = expf(-(xr * xr * 0.08f + yr * yr * 0.5f));
    }
    if (tid < 16) s_w1[tid] = w1[tid];
    if (tid < 8)  s_b1[tid] = b1[tid];
    if (tid < 32) s_w2[tid] = w2[tid];
    if (tid < 4)  s_b2[tid] = b2[tid];

    // Load halo tile with reflect padding, swizzled store.
    for (int i = tid; i < 14 * 38 * 4; i += 256) {
        int pl = i >> 2, g = i & 3;
        int ry = pl / 38, rx = pl - ry * 38;
        int gy = y0 + ry - 3; gy = gy < 0 ? -gy : (gy > 255 ? 510 - gy : gy);
        int gx = x0 + rx - 3; gx = gx < 0 ? -gx : (gx > 255 ? 510 - gx : gx);
        const float4* src = (const float4*)(g_xlow + ((size_t)((b << 16) + (gy << 8) + gx)) * 16);
        int slot = (g + (pl >> 1)) & 3;
        *(float4*)(s_x + pl * 16 + slot * 4) = src[g];
    }
    __syncthreads();

    // Deterministic per-kernel normalization sums.
    if (tid < 4) {
        float sum = 0.f;
        for (int t = 0; t < 49; t++) sum += s_base[tid * 49 + t];
        s_sinv[tid] = 1.f / sum;
    }
    __syncthreads();

    int px = x0 + tx, py = y0 + ty;

    // Per-pixel mixing weights: MLP(2->8->4) + softmax.
    float a = angle[(size_t)((b << 16) + (py << 8) + px)];
    float sn, cs;
    sincosf(2.f * a, &sn, &cs);
    float hb[8];
#pragma unroll
    for (int j = 0; j < 8; j++)
        hb[j] = fmaxf(0.f, fmaf(sn, s_w1[2 * j], fmaf(cs, s_w1[2 * j + 1], s_b1[j])));
    float lg[4];
#pragma unroll
    for (int o = 0; o < 4; o++) {
        float t = s_b2[o];
#pragma unroll
        for (int j = 0; j < 8; j++) t = fmaf(hb[j], s_w2[o * 8 + j], t);
        lg[o] = t;
    }
    float mx = fmaxf(fmaxf(lg[0], lg[1]), fmaxf(lg[2], lg[3]));
    float wk[4];
    float sum = 0.f;
#pragma unroll
    for (int o = 0; o < 4; o++) { wk[o] = expf(lg[o] - mx); sum += wk[o]; }
    float inv = 1.f / sum;
#pragma unroll
    for (int o = 0; o < 4; o++) wk[o] *= inv * s_sinv[o];  // fold base normalization

    // Combined per-pixel 7x7 kernel.
    float ck[49];
#pragma unroll
    for (int t = 0; t < 49; t++)
        ck[t] = fmaf(wk[3], s_base[147 + t],
                fmaf(wk[2], s_base[98 + t],
                fmaf(wk[1], s_base[49 + t], wk[0] * s_base[t])));

    u64 acc[8];
#pragma unroll
    for (int q = 0; q < 8; q++) acc[q] = 0ull;
    const ulonglong2* sx2 = (const ulonglong2*)s_x;

#pragma unroll
    for (int i = 0; i < 7; i++) {
#pragma unroll
        for (int j = 0; j < 7; j++) {
            int pl = (ty + i) * 38 + tx + j;
            int base4 = pl * 4;
            int r = (pl >> 1) & 3;
            u64 ckd = pack2(ck[i * 7 + j], ck[i * 7 + j]);
            ulonglong2 v0 = sx2[base4 + ((0 + r) & 3)];
            ulonglong2 v1 = sx2[base4 + ((1 + r) & 3)];
            ulonglong2 v2 = sx2[base4 + ((2 + r) & 3)];
            ulonglong2 v3 = sx2[base4 + ((3 + r) & 3)];
            fma2(acc[0], v0.x, ckd); fma2(acc[1], v0.y, ckd);
            fma2(acc[2], v1.x, ckd); fma2(acc[3], v1.y, ckd);
            fma2(acc[4], v2.x, ckd); fma2(acc[5], v2.y, ckd);
            fma2(acc[6], v3.x, ckd); fma2(acc[7], v3.y, ckd);
        }
    }

    ulonglong2* dst = (ulonglong2*)(g_outlow + (size_t)((b << 16) + (py << 8) + px) * 16);
    ulonglong2 r0; r0.x = acc[0]; r0.y = acc[1]; dst[0] = r0;
    ulonglong2 r1; r1.x = acc[2]; r1.y = acc[3]; dst[1] = r1;
    ulonglong2 r2; r2.x = acc[4]; r2.y = acc[5]; dst[2] = r2;
    ulonglong2 r3; r3.x = acc[6]; r3.y = acc[7]; dst[3] = r3;
}

// ---------------------------------------------------------------------------
// Kernel 3: 1x1 expand conv  outlow[b,p,m] * ew[c,m] -> out[b,c,h,w]
// 2 pixels/thread (px-pair f32x2 packing), 2 channel-groups of 128.
// grid (256, 2) x 256 threads.
// ---------------------------------------------------------------------------
__global__ __launch_bounds__(256) void k_expand(const float* __restrict__ ew,
                                                float* __restrict__ out) {
    __shared__ __align__(16) float2 s_ew[2048];  // [c_loc][m] dup-packed, 16 KB
    int tid = threadIdx.x;
    int c0 = blockIdx.y * 128;
    for (int i = tid; i < 2048; i += 256) {
        float v = ew[c0 * 16 + i];   // ew layout [c][m]
        s_ew[i] = make_float2(v, v);
    }
    __syncthreads();

    int pp = blockIdx.x * 256 + tid;  // pixel-pair id
    int gp = pp * 2;
    int b = gp >> 16, p = gp & 65535;

    const float4* src = (const float4*)(g_outlow + (size_t)gp * 16);
    float f[32];
#pragma unroll
    for (int q = 0; q < 8; q++) {
        float4 t = src[q];
        f[4 * q] = t.x; f[4 * q + 1] = t.y; f[4 * q + 2] = t.z; f[4 * q + 3] = t.w;
    }
    u64 xp[16];
#pragma unroll
    for (int m = 0; m < 16; m++) xp[m] = pack2(f[m], f[16 + m]);

    const ulonglong2* sew = (const ulonglong2*)s_ew;
    float* ob = out + (size_t)b * Cc * HWc + (size_t)c0 * HWc + p;

#pragma unroll 4
    for (int cl = 0; cl < 128; cl++) {
        u64 a0 = 0ull, a1 = 0ull;
#pragma unroll
        for (int mm = 0; mm < 8; mm++) {
            ulonglong2 w = sew[cl * 8 + mm];
            fma2(a0, xp[2 * mm],     w.x);
            fma2(a1, xp[2 * mm + 1], w.y);
        }
        u64 r = add2(a0, a1);
        *(u64*)(ob + (size_t)cl * HWc) = r;
    }
}

// ---------------------------------------------------------------------------
extern "C" void kernel_launch(void* const* d_in, const int* in_sizes, int n_in,
                              void* d_out, int out_size) {
    const float* x     = (const float*)d_in[0];
    const float* angle = (const float*)d_in[1];
    const float* rw    = (const float*)d_in[2];
    const float* ew    = (const float*)d_in[3];
    const float* w1    = (const float*)d_in[4];
    const float* b1    = (const float*)d_in[5];
    const float* w2    = (const float*)d_in[6];
    const float* b2    = (const float*)d_in[7];
    float* out = (float*)d_out;

    k_reduce<<<512, 256>>>(x, rw);
    k_conv<<<dim3(8, 32, 2), dim3(32, 8)>>>(angle, w1, b1, w2, b2);
    k_expand<<<dim3(256, 2), 256>>>(ew, out);
}

// round 6
// speedup vs baseline: 1.1843x; 1.0017x over previous
#include <cuda_runtime.h>
#include <cuda_bf16.h>
#include <math_constants.h>

#define Bc 2
#define Cc 256
#define Hc 256
#define Wc 256
#define MIDc 16
#define HWc 65536

typedef unsigned long long u64;

__device__ float g_xlow[(size_t)Bc * HWc * MIDc];    // [b][p][m] interleaved
__device__ float g_outlow[(size_t)Bc * HWc * MIDc];  // [b][p][m] interleaved

__device__ __forceinline__ u64 pack2(float lo, float hi) {
    u64 r; asm("mov.b64 %0, {%1,%2};" : "=l"(r) : "f"(lo), "f"(hi)); return r;
}
__device__ __forceinline__ void unpack2(u64 v, float& lo, float& hi) {
    asm("mov.b64 {%0,%1}, %2;" : "=f"(lo), "=f"(hi) : "l"(v));
}
__device__ __forceinline__ void fma2(u64& d, u64 a, u64 b) {
    asm("fma.rn.f32x2 %0, %1, %2, %0;" : "+l"(d) : "l"(a), "l"(b));
}
__device__ __forceinline__ u64 add2(u64 a, u64 b) {
    u64 r; asm("add.rn.f32x2 %0, %1, %2;" : "=l"(r) : "l"(a), "l"(b)); return r;
}

// ---------------------------------------------------------------------------
// Kernel 1: 1x1 reduce conv  x[b,c,h,w] * rw[m,c] -> xlow[b,p,m] (interleaved)
// 4 pixels/thread: weight LDS amortized 4x (crossbar was the binder at 58us).
// 256 blocks x 128 threads.
// ---------------------------------------------------------------------------
__global__ __launch_bounds__(128) void k_reduce(const float* __restrict__ x,
                                                const float* __restrict__ rw) {
    __shared__ __align__(16) float s_rw[4096];  // [c][m], 16 KB
    int tid = threadIdx.x;
    for (int i = tid; i < 4096; i += 128) {
        int c = i >> 4, m = i & 15;
        s_rw[i] = rw[m * 256 + c];
    }
    __syncthreads();

    int gp4 = (blockIdx.x * 128 + tid) * 4;     // base pixel over B*HW
    int b = gp4 >> 16, p = gp4 & 65535;
    const float* xb = x + (size_t)b * (Cc * HWc) + p;
    const ulonglong2* srw = (const ulonglong2*)s_rw;

    u64 acc[4][8];
#pragma unroll
    for (int px = 0; px < 4; px++)
#pragma unroll
        for (int m = 0; m < 8; m++) acc[px][m] = 0ull;

#pragma unroll 8
    for (int c = 0; c < 256; c++) {
        float4 xv = *(const float4*)(xb + (size_t)c * HWc);
        u64 xd0 = pack2(xv.x, xv.x);
        u64 xd1 = pack2(xv.y, xv.y);
        u64 xd2 = pack2(xv.z, xv.z);
        u64 xd3 = pack2(xv.w, xv.w);
        ulonglong2 w0 = srw[c * 4 + 0];
        ulonglong2 w1 = srw[c * 4 + 1];
        ulonglong2 w2 = srw[c * 4 + 2];
        ulonglong2 w3 = srw[c * 4 + 3];
        fma2(acc[0][0], xd0, w0.x); fma2(acc[0][1], xd0, w0.y);
        fma2(acc[0][2], xd0, w1.x); fma2(acc[0][3], xd0, w1.y);
        fma2(acc[0][4], xd0, w2.x); fma2(acc[0][5], xd0, w2.y);
        fma2(acc[0][6], xd0, w3.x); fma2(acc[0][7], xd0, w3.y);
        fma2(acc[1][0], xd1, w0.x); fma2(acc[1][1], xd1, w0.y);
        fma2(acc[1][2], xd1, w1.x); fma2(acc[1][3], xd1, w1.y);
        fma2(acc[1][4], xd1, w2.x); fma2(acc[1][5], xd1, w2.y);
        fma2(acc[1][6], xd1, w3.x); fma2(acc[1][7], xd1, w3.y);
        fma2(acc[2][0], xd2, w0.x); fma2(acc[2][1], xd2, w0.y);
        fma2(acc[2][2], xd2, w1.x); fma2(acc[2][3], xd2, w1.y);
        fma2(acc[2][4], xd2, w2.x); fma2(acc[2][5], xd2, w2.y);
        fma2(acc[2][6], xd2, w3.x); fma2(acc[2][7], xd2, w3.y);
        fma2(acc[3][0], xd3, w0.x); fma2(acc[3][1], xd3, w0.y);
        fma2(acc[3][2], xd3, w1.x); fma2(acc[3][3], xd3, w1.y);
        fma2(acc[3][4], xd3, w2.x); fma2(acc[3][5], xd3, w2.y);
        fma2(acc[3][6], xd3, w3.x); fma2(acc[3][7], xd3, w3.y);
    }

#pragma unroll
    for (int px = 0; px < 4; px++) {
        ulonglong2* dst = (ulonglong2*)(g_xlow + (size_t)(gp4 + px) * 16);
        ulonglong2 r0; r0.x = acc[px][0]; r0.y = acc[px][1]; dst[0] = r0;
        ulonglong2 r1; r1.x = acc[px][2]; r1.y = acc[px][3]; dst[1] = r1;
        ulonglong2 r2; r2.x = acc[px][4]; r2.y = acc[px][5]; dst[2] = r2;
        ulonglong2 r3; r3.x = acc[px][6]; r3.y = acc[px][7]; dst[3] = r3;
    }
}

// ---------------------------------------------------------------------------
// Kernel 2: fused base-kernel build + angle-MLP + softmax + 7x7 directional
// conv. Tile 32x8 pixels, halo 3 (reflect), 16 channels in smem with rotation
// swizzle for conflict-free LDS.128.
// ---------------------------------------------------------------------------
__global__ __launch_bounds__(256) void k_conv(const float* __restrict__ angle,
                                              const float* __restrict__ w1,
                                              const float* __restrict__ b1,
                                              const float* __restrict__ w2,
                                              const float* __restrict__ b2) {
    __shared__ __align__(16) float s_x[14 * 38 * 16];  // 34 KB, swizzled
    __shared__ float s_base[196];
    __shared__ float s_sinv[4];
    __shared__ float s_w1[16], s_b1[8], s_w2[32], s_b2[4];

    int tx = threadIdx.x, ty = threadIdx.y;
    int tid = ty * 32 + tx;
    int x0 = blockIdx.x * 32, y0 = blockIdx.y * 8, b = blockIdx.z;

    // Build the 4 oriented anisotropic Gaussian kernels (unnormalized).
    if (tid < 196) {
        int k = tid / 49, r = tid - k * 49;
        int ii = r / 7 - 3, jj = r % 7 - 3;
        float theta = (float)k * (float)(CUDART_PI / 4.0);
        float cth, sth;
        sincosf(theta, &sth, &cth);
        float xr = (float)ii * cth + (float)jj * sth;
        float yr = -(float)ii * sth + (float)jj * cth;
        s_base[tid] = expf(-(xr * xr * 0.08f + yr * yr * 0.5f));
    }
    if (tid < 16) s_w1[tid] = w1[tid];
    if (tid < 8)  s_b1[tid] = b1[tid];
    if (tid < 32) s_w2[tid] = w2[tid];
    if (tid < 4)  s_b2[tid] = b2[tid];

    // Load halo tile with reflect padding, swizzled store.
    for (int i = tid; i < 14 * 38 * 4; i += 256) {
        int pl = i >> 2, g = i & 3;
        int ry = pl / 38, rx = pl - ry * 38;
        int gy = y0 + ry - 3; gy = gy < 0 ? -gy : (gy > 255 ? 510 - gy : gy);
        int gx = x0 + rx - 3; gx = gx < 0 ? -gx : (gx > 255 ? 510 - gx : gx);
        const float4* src = (const float4*)(g_xlow + ((size_t)((b << 16) + (gy << 8) + gx)) * 16);
        int slot = (g + (pl >> 1)) & 3;
        *(float4*)(s_x + pl * 16 + slot * 4) = src[g];
    }
    __syncthreads();

    // Deterministic per-kernel normalization sums.
    if (tid < 4) {
        float sum = 0.f;
        for (int t = 0; t < 49; t++) sum += s_base[tid * 49 + t];
        s_sinv[tid] = 1.f / sum;
    }
    __syncthreads();

    int px = x0 + tx, py = y0 + ty;

    // Per-pixel mixing weights: MLP(2->8->4) + softmax.
    float a = angle[(size_t)((b << 16) + (py << 8) + px)];
    float sn, cs;
    sincosf(2.f * a, &sn, &cs);
    float hb[8];
#pragma unroll
    for (int j = 0; j < 8; j++)
        hb[j] = fmaxf(0.f, fmaf(sn, s_w1[2 * j], fmaf(cs, s_w1[2 * j + 1], s_b1[j])));
    float lg[4];
#pragma unroll
    for (int o = 0; o < 4; o++) {
        float t = s_b2[o];
#pragma unroll
        for (int j = 0; j < 8; j++) t = fmaf(hb[j], s_w2[o * 8 + j], t);
        lg[o] = t;
    }
    float mx = fmaxf(fmaxf(lg[0], lg[1]), fmaxf(lg[2], lg[3]));
    float wk[4];
    float sum = 0.f;
#pragma unroll
    for (int o = 0; o < 4; o++) { wk[o] = expf(lg[o] - mx); sum += wk[o]; }
    float inv = 1.f / sum;
#pragma unroll
    for (int o = 0; o < 4; o++) wk[o] *= inv * s_sinv[o];  // fold base normalization

    // Combined per-pixel 7x7 kernel.
    float ck[49];
#pragma unroll
    for (int t = 0; t < 49; t++)
        ck[t] = fmaf(wk[3], s_base[147 + t],
                fmaf(wk[2], s_base[98 + t],
                fmaf(wk[1], s_base[49 + t], wk[0] * s_base[t])));

    u64 acc[8];
#pragma unroll
    for (int q = 0; q < 8; q++) acc[q] = 0ull;
    const ulonglong2* sx2 = (const ulonglong2*)s_x;

#pragma unroll
    for (int i = 0; i < 7; i++) {
#pragma unroll
        for (int j = 0; j < 7; j++) {
            int pl = (ty + i) * 38 + tx + j;
            int base4 = pl * 4;
            int r = (pl >> 1) & 3;
            u64 ckd = pack2(ck[i * 7 + j], ck[i * 7 + j]);
            ulonglong2 v0 = sx2[base4 + ((0 + r) & 3)];
            ulonglong2 v1 = sx2[base4 + ((1 + r) & 3)];
            ulonglong2 v2 = sx2[base4 + ((2 + r) & 3)];
            ulonglong2 v3 = sx2[base4 + ((3 + r) & 3)];
            fma2(acc[0], v0.x, ckd); fma2(acc[1], v0.y, ckd);
            fma2(acc[2], v1.x, ckd); fma2(acc[3], v1.y, ckd);
            fma2(acc[4], v2.x, ckd); fma2(acc[5], v2.y, ckd);
            fma2(acc[6], v3.x, ckd); fma2(acc[7], v3.y, ckd);
        }
    }

    ulonglong2* dst = (ulonglong2*)(g_outlow + (size_t)((b << 16) + (py << 8) + px) * 16);
    ulonglong2 r0; r0.x = acc[0]; r0.y = acc[1]; dst[0] = r0;
    ulonglong2 r1; r1.x = acc[2]; r1.y = acc[3]; dst[1] = r1;
    ulonglong2 r2; r2.x = acc[4]; r2.y = acc[5]; dst[2] = r2;
    ulonglong2 r3; r3.x = acc[6]; r3.y = acc[7]; dst[3] = r3;
}

// ---------------------------------------------------------------------------
// Kernel 3: 1x1 expand conv  outlow[b,p,m] * ew[c,m] -> out[b,c,h,w]
// 4 pixels/thread, m-pair f32x2 packing (weights non-dup: 4 LDS.128/channel
// amortized over 4 pixels), horizontal add, STG.128 per channel.
// grid (128, 2) x 256 threads.
// ---------------------------------------------------------------------------
__global__ __launch_bounds__(256) void k_expand(const float* __restrict__ ew,
                                                float* __restrict__ out) {
    __shared__ __align__(16) float s_ew[2048];  // [c_loc][m], 8 KB
    int tid = threadIdx.x;
    int c0 = blockIdx.y * 128;
    for (int i = tid; i < 2048; i += 256) s_ew[i] = ew[c0 * 16 + i];
    __syncthreads();

    int gp4 = (blockIdx.x * 256 + tid) * 4;     // base pixel over B*HW
    int b = gp4 >> 16, p = gp4 & 65535;

    // Load 4 pixels x 16 mids; memory already pairs (m0,m1) in adjacent floats.
    u64 xp[4][8];
#pragma unroll
    for (int px = 0; px < 4; px++) {
        const ulonglong2* s2 = (const ulonglong2*)(g_outlow + (size_t)(gp4 + px) * 16);
        ulonglong2 t0 = s2[0], t1 = s2[1], t2 = s2[2], t3 = s2[3];
        xp[px][0] = t0.x; xp[px][1] = t0.y;
        xp[px][2] = t1.x; xp[px][3] = t1.y;
        xp[px][4] = t2.x; xp[px][5] = t2.y;
        xp[px][6] = t3.x; xp[px][7] = t3.y;
    }

    const ulonglong2* sew = (const ulonglong2*)s_ew;
    float* ob = out + (size_t)b * (Cc * HWc) + (size_t)c0 * HWc + p;

#pragma unroll 4
    for (int cl = 0; cl < 128; cl++) {
        ulonglong2 w0 = sew[cl * 4 + 0];
        ulonglong2 w1 = sew[cl * 4 + 1];
        ulonglong2 w2 = sew[cl * 4 + 2];
        ulonglong2 w3 = sew[cl * 4 + 3];
        float4 r;
#pragma unroll
        for (int px = 0; px < 4; px++) {
            u64 a = 0ull;
            fma2(a, xp[px][0], w0.x); fma2(a, xp[px][1], w0.y);
            fma2(a, xp[px][2], w1.x); fma2(a, xp[px][3], w1.y);
            fma2(a, xp[px][4], w2.x); fma2(a, xp[px][5], w2.y);
            fma2(a, xp[px][6], w3.x); fma2(a, xp[px][7], w3.y);
            float lo, hi; unpack2(a, lo, hi);
            float v = lo + hi;
            if (px == 0) r.x = v; else if (px == 1) r.y = v;
            else if (px == 2) r.z = v; else r.w = v;
        }
        *(float4*)(ob + (size_t)cl * HWc) = r;
    }
}

// ---------------------------------------------------------------------------
extern "C" void kernel_launch(void* const* d_in, const int* in_sizes, int n_in,
                              void* d_out, int out_size) {
    const float* x     = (const float*)d_in[0];
    const float* angle = (const float*)d_in[1];
    const float* rw    = (const float*)d_in[2];
    const float* ew    = (const float*)d_in[3];
    const float* w1    = (const float*)d_in[4];
    const float* b1    = (const float*)d_in[5];
    const float* w2    = (const float*)d_in[6];
    const float* b2    = (const float*)d_in[7];
    float* out = (float*)d_out;

    k_reduce<<<256, 128>>>(x, rw);
    k_conv<<<dim3(8, 32, 2), dim3(32, 8)>>>(angle, w1, b1, w2, b2);
    k_expand<<<dim3(128, 2), 256>>>(ew, out);
}

// round 7
// speedup vs baseline: 1.4397x; 1.2157x over previous
#include <cuda_runtime.h>
#include <cuda_bf16.h>
#include <math_constants.h>

#define Bc 2
#define Cc 256
#define Hc 256
#define Wc 256
#define MIDc 16
#define HWc 65536
#define PARTSZ ((size_t)Bc * HWc * MIDc)   // 2M floats per channel-slice partial

typedef unsigned long long u64;

__device__ float g_xpart[4 * PARTSZ];        // 4 channel-slice partials of xlow
__device__ float g_outlow[PARTSZ];           // [b][p][m] interleaved

__device__ __forceinline__ u64 pack2(float lo, float hi) {
    u64 r; asm("mov.b64 %0, {%1,%2};" : "=l"(r) : "f"(lo), "f"(hi)); return r;
}
__device__ __forceinline__ void unpack2(u64 v, float& lo, float& hi) {
    asm("mov.b64 {%0,%1}, %2;" : "=f"(lo), "=f"(hi) : "l"(v));
}
__device__ __forceinline__ void fma2(u64& d, u64 a, u64 b) {
    asm("fma.rn.f32x2 %0, %1, %2, %0;" : "+l"(d) : "l"(a), "l"(b));
}
__device__ __forceinline__ u64 add2(u64 a, u64 b) {
    u64 r; asm("add.rn.f32x2 %0, %1, %2;" : "=l"(r) : "l"(a), "l"(b)); return r;
}

// ---------------------------------------------------------------------------
// Kernel 1: 1x1 reduce conv, channel-split 4 ways.
// grid (128, 4) x 256 threads. Each thread: 4 pixels x 64 channels -> partial.
// Weight LDS amortized over 4 px; 131072 threads for latency hiding.
// ---------------------------------------------------------------------------
__global__ __launch_bounds__(256) void k_reduce(const float* __restrict__ x,
                                                const float* __restrict__ rw) {
    __shared__ __align__(16) float s_rw[1024];  // this slice: [c_loc][m], 4 KB
    int tid = threadIdx.x;
    int cs = blockIdx.y;
    int c0 = cs * 64;
    for (int i = tid; i < 1024; i += 256) {
        int cl = i >> 4, m = i & 15;
        s_rw[i] = rw[m * 256 + c0 + cl];
    }
    __syncthreads();

    int gp4 = (blockIdx.x * 256 + tid) * 4;     // base pixel over B*HW
    int b = gp4 >> 16, p = gp4 & 65535;
    const float* xb = x + (size_t)b * (Cc * HWc) + (size_t)c0 * HWc + p;
    const ulonglong2* srw = (const ulonglong2*)s_rw;

    u64 acc[4][8];
#pragma unroll
    for (int px = 0; px < 4; px++)
#pragma unroll
        for (int m = 0; m < 8; m++) acc[px][m] = 0ull;

#pragma unroll 4
    for (int cl = 0; cl < 64; cl++) {
        float4 xv = *(const float4*)(xb + (size_t)cl * HWc);
        u64 xd0 = pack2(xv.x, xv.x);
        u64 xd1 = pack2(xv.y, xv.y);
        u64 xd2 = pack2(xv.z, xv.z);
        u64 xd3 = pack2(xv.w, xv.w);
        ulonglong2 w0 = srw[cl * 4 + 0];
        ulonglong2 w1 = srw[cl * 4 + 1];
        ulonglong2 w2 = srw[cl * 4 + 2];
        ulonglong2 w3 = srw[cl * 4 + 3];
        fma2(acc[0][0], xd0, w0.x); fma2(acc[0][1], xd0, w0.y);
        fma2(acc[0][2], xd0, w1.x); fma2(acc[0][3], xd0, w1.y);
        fma2(acc[0][4], xd0, w2.x); fma2(acc[0][5], xd0, w2.y);
        fma2(acc[0][6], xd0, w3.x); fma2(acc[0][7], xd0, w3.y);
        fma2(acc[1][0], xd1, w0.x); fma2(acc[1][1], xd1, w0.y);
        fma2(acc[1][2], xd1, w1.x); fma2(acc[1][3], xd1, w1.y);
        fma2(acc[1][4], xd1, w2.x); fma2(acc[1][5], xd1, w2.y);
        fma2(acc[1][6], xd1, w3.x); fma2(acc[1][7], xd1, w3.y);
        fma2(acc[2][0], xd2, w0.x); fma2(acc[2][1], xd2, w0.y);
        fma2(acc[2][2], xd2, w1.x); fma2(acc[2][3], xd2, w1.y);
        fma2(acc[2][4], xd2, w2.x); fma2(acc[2][5], xd2, w2.y);
        fma2(acc[2][6], xd2, w3.x); fma2(acc[2][7], xd2, w3.y);
        fma2(acc[3][0], xd3, w0.x); fma2(acc[3][1], xd3, w0.y);
        fma2(acc[3][2], xd3, w1.x); fma2(acc[3][3], xd3, w1.y);
        fma2(acc[3][4], xd3, w2.x); fma2(acc[3][5], xd3, w2.y);
        fma2(acc[3][6], xd3, w3.x); fma2(acc[3][7], xd3, w3.y);
    }

    float* outp = g_xpart + (size_t)cs * PARTSZ;
#pragma unroll
    for (int px = 0; px < 4; px++) {
        ulonglong2* dst = (ulonglong2*)(outp + (size_t)(gp4 + px) * 16);
        ulonglong2 r0; r0.x = acc[px][0]; r0.y = acc[px][1]; dst[0] = r0;
        ulonglong2 r1; r1.x = acc[px][2]; r1.y = acc[px][3]; dst[1] = r1;
        ulonglong2 r2; r2.x = acc[px][4]; r2.y = acc[px][5]; dst[2] = r2;
        ulonglong2 r3; r3.x = acc[px][6]; r3.y = acc[px][7]; dst[3] = r3;
    }
}

// ---------------------------------------------------------------------------
// Kernel 2: fused base-kernel build + angle-MLP + softmax + 7x7 directional
// conv. Sums the 4 reduce partials during the smem halo fill.
// ---------------------------------------------------------------------------
__global__ __launch_bounds__(256) void k_conv(const float* __restrict__ angle,
                                              const float* __restrict__ w1,
                                              const float* __restrict__ b1,
                                              const float* __restrict__ w2,
                                              const float* __restrict__ b2) {
    __shared__ __align__(16) float s_x[14 * 38 * 16];  // 34 KB, swizzled
    __shared__ float s_base[196];
    __shared__ float s_sinv[4];
    __shared__ float s_w1[16], s_b1[8], s_w2[32], s_b2[4];

    int tx = threadIdx.x, ty = threadIdx.y;
    int tid = ty * 32 + tx;
    int x0 = blockIdx.x * 32, y0 = blockIdx.y * 8, b = blockIdx.z;

    // Build the 4 oriented anisotropic Gaussian kernels (unnormalized).
    if (tid < 196) {
        int k = tid / 49, r = tid - k * 49;
        int ii = r / 7 - 3, jj = r % 7 - 3;
        float theta = (float)k * (float)(CUDART_PI / 4.0);
        float cth, sth;
        sincosf(theta, &sth, &cth);
        float xr = (float)ii * cth + (float)jj * sth;
        float yr = -(float)ii * sth + (float)jj * cth;
        s_base[tid] = expf(-(xr * xr * 0.08f + yr * yr * 0.5f));
    }
    if (tid < 16) s_w1[tid] = w1[tid];
    if (tid < 8)  s_b1[tid] = b1[tid];
    if (tid < 32) s_w2[tid] = w2[tid];
    if (tid < 4)  s_b2[tid] = b2[tid];

    // Load halo tile with reflect padding, summing the 4 channel-slice
    // partials; swizzled store.
    for (int i = tid; i < 14 * 38 * 4; i += 256) {
        int pl = i >> 2, g = i & 3;
        int ry = pl / 38, rx = pl - ry * 38;
        int gy = y0 + ry - 3; gy = gy < 0 ? -gy : (gy > 255 ? 510 - gy : gy);
        int gx = x0 + rx - 3; gx = gx < 0 ? -gx : (gx > 255 ? 510 - gx : gx);
        size_t off = ((size_t)((b << 16) + (gy << 8) + gx)) * 16 + g * 4;
        ulonglong2 v0 = *(const ulonglong2*)(g_xpart + off);
        ulonglong2 v1 = *(const ulonglong2*)(g_xpart + PARTSZ + off);
        ulonglong2 v2 = *(const ulonglong2*)(g_xpart + 2 * PARTSZ + off);
        ulonglong2 v3 = *(const ulonglong2*)(g_xpart + 3 * PARTSZ + off);
        ulonglong2 s;
        s.x = add2(add2(v0.x, v1.x), add2(v2.x, v3.x));
        s.y = add2(add2(v0.y, v1.y), add2(v2.y, v3.y));
        int slot = (g + (pl >> 1)) & 3;
        *(ulonglong2*)(s_x + pl * 16 + slot * 4) = s;
    }
    __syncthreads();

    // Deterministic per-kernel normalization sums.
    if (tid < 4) {
        float sum = 0.f;
        for (int t = 0; t < 49; t++) sum += s_base[tid * 49 + t];
        s_sinv[tid] = 1.f / sum;
    }
    __syncthreads();

    int px = x0 + tx, py = y0 + ty;

    // Per-pixel mixing weights: MLP(2->8->4) + softmax.
    float a = angle[(size_t)((b << 16) + (py << 8) + px)];
    float sn, cs;
    sincosf(2.f * a, &sn, &cs);
    float hb[8];
#pragma unroll
    for (int j = 0; j < 8; j++)
        hb[j] = fmaxf(0.f, fmaf(sn, s_w1[2 * j], fmaf(cs, s_w1[2 * j + 1], s_b1[j])));
    float lg[4];
#pragma unroll
    for (int o = 0; o < 4; o++) {
        float t = s_b2[o];
#pragma unroll
        for (int j = 0; j < 8; j++) t = fmaf(hb[j], s_w2[o * 8 + j], t);
        lg[o] = t;
    }
    float mx = fmaxf(fmaxf(lg[0], lg[1]), fmaxf(lg[2], lg[3]));
    float wk[4];
    float sum = 0.f;
#pragma unroll
    for (int o = 0; o < 4; o++) { wk[o] = expf(lg[o] - mx); sum += wk[o]; }
    float inv = 1.f / sum;
#pragma unroll
    for (int o = 0; o < 4; o++) wk[o] *= inv * s_sinv[o];  // fold base normalization

    // Combined per-pixel 7x7 kernel.
    float ck[49];
#pragma unroll
    for (int t = 0; t < 49; t++)
        ck[t] = fmaf(wk[3], s_base[147 + t],
                fmaf(wk[2], s_base[98 + t],
                fmaf(wk[1], s_base[49 + t], wk[0] * s_base[t])));

    u64 acc[8];
#pragma unroll
    for (int q = 0; q < 8; q++) acc[q] = 0ull;
    const ulonglong2* sx2 = (const ulonglong2*)s_x;

#pragma unroll
    for (int i = 0; i < 7; i++) {
#pragma unroll
        for (int j = 0; j < 7; j++) {
            int pl = (ty + i) * 38 + tx + j;
            int base4 = pl * 4;
            int r = (pl >> 1) & 3;
            u64 ckd = pack2(ck[i * 7 + j], ck[i * 7 + j]);
            ulonglong2 v0 = sx2[base4 + ((0 + r) & 3)];
            ulonglong2 v1 = sx2[base4 + ((1 + r) & 3)];
            ulonglong2 v2 = sx2[base4 + ((2 + r) & 3)];
            ulonglong2 v3 = sx2[base4 + ((3 + r) & 3)];
            fma2(acc[0], v0.x, ckd); fma2(acc[1], v0.y, ckd);
            fma2(acc[2], v1.x, ckd); fma2(acc[3], v1.y, ckd);
            fma2(acc[4], v2.x, ckd); fma2(acc[5], v2.y, ckd);
            fma2(acc[6], v3.x, ckd); fma2(acc[7], v3.y, ckd);
        }
    }

    ulonglong2* dst = (ulonglong2*)(g_outlow + (size_t)((b << 16) + (py << 8) + px) * 16);
    ulonglong2 r0; r0.x = acc[0]; r0.y = acc[1]; dst[0] = r0;
    ulonglong2 r1; r1.x = acc[2]; r1.y = acc[3]; dst[1] = r1;
    ulonglong2 r2; r2.x = acc[4]; r2.y = acc[5]; dst[2] = r2;
    ulonglong2 r3; r3.x = acc[6]; r3.y = acc[7]; dst[3] = r3;
}

// ---------------------------------------------------------------------------
// Kernel 3: 1x1 expand conv  outlow[b,p,m] * ew[c,m] -> out[b,c,h,w]
// 4 pixels/thread, 4 channel-groups of 64: 131072 threads total.
// grid (128, 4) x 256 threads.
// ---------------------------------------------------------------------------
__global__ __launch_bounds__(256) void k_expand(const float* __restrict__ ew,
                                                float* __restrict__ out) {
    __shared__ __align__(16) float s_ew[1024];  // [c_loc][m], 4 KB
    int tid = threadIdx.x;
    int c0 = blockIdx.y * 64;
    for (int i = tid; i < 1024; i += 256) s_ew[i] = ew[c0 * 16 + i];
    __syncthreads();

    int gp4 = (blockIdx.x * 256 + tid) * 4;     // base pixel over B*HW
    int b = gp4 >> 16, p = gp4 & 65535;

    // Load 4 pixels x 16 mids; memory already pairs (m0,m1) in adjacent floats.
    u64 xp[4][8];
#pragma unroll
    for (int px = 0; px < 4; px++) {
        const ulonglong2* s2 = (const ulonglong2*)(g_outlow + (size_t)(gp4 + px) * 16);
        ulonglong2 t0 = s2[0], t1 = s2[1], t2 = s2[2], t3 = s2[3];
        xp[px][0] = t0.x; xp[px][1] = t0.y;
        xp[px][2] = t1.x; xp[px][3] = t1.y;
        xp[px][4] = t2.x; xp[px][5] = t2.y;
        xp[px][6] = t3.x; xp[px][7] = t3.y;
    }

    const ulonglong2* sew = (const ulonglong2*)s_ew;
    float* ob = out + (size_t)b * (Cc * HWc) + (size_t)c0 * HWc + p;

#pragma unroll 4
    for (int cl = 0; cl < 64; cl++) {
        ulonglong2 w0 = sew[cl * 4 + 0];
        ulonglong2 w1 = sew[cl * 4 + 1];
        ulonglong2 w2 = sew[cl * 4 + 2];
        ulonglong2 w3 = sew[cl * 4 + 3];
        float4 r;
#pragma unroll
        for (int px = 0; px < 4; px++) {
            u64 a = 0ull;
            fma2(a, xp[px][0], w0.x); fma2(a, xp[px][1], w0.y);
            fma2(a, xp[px][2], w1.x); fma2(a, xp[px][3], w1.y);
            fma2(a, xp[px][4], w2.x); fma2(a, xp[px][5], w2.y);
            fma2(a, xp[px][6], w3.x); fma2(a, xp[px][7], w3.y);
            float lo, hi; unpack2(a, lo, hi);
            float v = lo + hi;
            if (px == 0) r.x = v; else if (px == 1) r.y = v;
            else if (px == 2) r.z = v; else r.w = v;
        }
        *(float4*)(ob + (size_t)cl * HWc) = r;
    }
}

// ---------------------------------------------------------------------------
extern "C" void kernel_launch(void* const* d_in, const int* in_sizes, int n_in,
                              void* d_out, int out_size) {
    const float* x     = (const float*)d_in[0];
    const float* angle = (const float*)d_in[1];
    const float* rw    = (const float*)d_in[2];
    const float* ew    = (const float*)d_in[3];
    const float* w1    = (const float*)d_in[4];
    const float* b1    = (const float*)d_in[5];
    const float* w2    = (const float*)d_in[6];
    const float* b2    = (const float*)d_in[7];
    float* out = (float*)d_out;

    k_reduce<<<dim3(128, 4), 256>>>(x, rw);
    k_conv<<<dim3(8, 32, 2), dim3(32, 8)>>>(angle, w1, b1, w2, b2);
    k_expand<<<dim3(128, 4), 256>>>(ew, out);
}